// round 12
// baseline (speedup 1.0000x reference)
#include <cuda_runtime.h>
#include <cstdint>

#define B_  2
#define C_  512
#define NH  8
#define D_  64
#define S_  2304
#define SCALE 0.125f
#define QT  128

// ---------------------------------------------------------------------------
// k-permuted m16n8k8 tf32 mma: thread tig supplies k-slots {2tig, 2tig+1}
// (applied consistently to A and B, so the contraction is unchanged).
// A regs (a_lo.x,a_lo.y) = A[row+gid][kk+2tig .. +1], (a_hi) same row+8.
// B regs (b.x,b.y)       = B[n=col][kk+2tig .. +1] from an [n][k] tile.
// reg order for PTX: {a0,a1,a2,a3} = {lo.x, hi.x, lo.y, hi.y}; {b0,b1}={x,y}.
// ---------------------------------------------------------------------------
__device__ __forceinline__ float tf32r(float f) {
    unsigned r; asm("cvt.rna.tf32.f32 %0, %1;" : "=r"(r) : "f"(f));
    return __uint_as_float(r);
}
__device__ __forceinline__ void mma_tf32(float c[4],
                                         float a0, float a1, float a2, float a3,
                                         float b0, float b1) {
    asm volatile(
        "mma.sync.aligned.m16n8k8.row.col.f32.tf32.tf32.f32 "
        "{%0,%1,%2,%3}, {%4,%5,%6,%7}, {%8,%9}, {%0,%1,%2,%3};\n"
        : "+f"(c[0]), "+f"(c[1]), "+f"(c[2]), "+f"(c[3])
        : "r"(__float_as_uint(a0)), "r"(__float_as_uint(a1)),
          "r"(__float_as_uint(a2)), "r"(__float_as_uint(a3)),
          "r"(__float_as_uint(b0)), "r"(__float_as_uint(b1)));
}

// Scratch ------------------------------------------------------------------
__device__ float g_q[B_ * NH * S_ * D_];    // [bn][s][d]  (scale folded)
__device__ float g_k[B_ * NH * S_ * D_];    // [bn][s][d]
__device__ float g_v[B_ * NH * D_ * S_];    // [bn][d][s]
__device__ float g_attn[B_ * S_ * NH * D_]; // [b][s][n*64+d]

// ===========================================================================
// QKV projection (CTA 64d x 64s, warp 32x32, k-chunk 32).
// A = W[d][c] (As stride 40), B = x[c][s] (Bs stride 68, scalar b reads).
// Q/K -> [s][d] via smem-staged float4; V -> [d][s] direct float2.
// grid (36, 16, 3), block 128.
// ===========================================================================
__global__ __launch_bounds__(128) void proj_kernel(
    const float* __restrict__ x,
    const float* __restrict__ Wq, const float* __restrict__ bq,
    const float* __restrict__ Wk, const float* __restrict__ bk,
    const float* __restrict__ Wv, const float* __restrict__ bv)
{
    __shared__ float sbuf[4736];                 // As(2560) | Bs(2176); Ts(4352)
    float (*As)[40] = (float (*)[40])sbuf;
    float (*Bs)[68] = (float (*)[68])(sbuf + 2560);
    float (*Ts)[68] = (float (*)[68])sbuf;       // epilogue staging [s][d]

    const int p  = blockIdx.z;
    const int bn = blockIdx.y;
    const int b  = bn >> 3, n = bn & 7;
    const int s0 = blockIdx.x * 64;

    const float* W    = (p == 0) ? Wq : (p == 1) ? Wk : Wv;
    const float* bias = (p == 0) ? bq : (p == 1) ? bk : bv;

    const int tid  = threadIdx.x;
    const int wid  = tid >> 5, lane = tid & 31;
    const int gid  = lane >> 2, tig = lane & 3;
    const int wm   = wid >> 1, wn = wid & 1;

    const float* xb = x + (size_t)b * C_ * S_ + s0;
    const float* Wn = W + n * D_ * C_;

    float Cacc[2][4][4] = {};

    for (int k0 = 0; k0 < C_; k0 += 32) {
        #pragma unroll
        for (int r = 0; r < 4; r++) {
            int i4 = tid + r * 128;
            int dd = i4 >> 3, c4 = (i4 & 7) * 4;
            float4 v = *(const float4*)&Wn[dd * C_ + k0 + c4];
            As[dd][c4]     = tf32r(v.x); As[dd][c4 + 1] = tf32r(v.y);
            As[dd][c4 + 2] = tf32r(v.z); As[dd][c4 + 3] = tf32r(v.w);
        }
        #pragma unroll
        for (int r = 0; r < 4; r++) {
            int i4 = tid + r * 128;
            int cc = i4 >> 4, s4 = (i4 & 15) * 4;
            float4 v = *(const float4*)&xb[(size_t)(k0 + cc) * S_ + s4];
            Bs[cc][s4]     = tf32r(v.x); Bs[cc][s4 + 1] = tf32r(v.y);
            Bs[cc][s4 + 2] = tf32r(v.z); Bs[cc][s4 + 3] = tf32r(v.w);
        }
        __syncthreads();

        #pragma unroll
        for (int kk = 0; kk < 32; kk += 8) {
            float2 alo[2], ahi[2];
            #pragma unroll
            for (int i = 0; i < 2; i++) {
                int row = wm * 32 + i * 16 + gid;
                alo[i] = *(const float2*)&As[row][kk + 2 * tig];
                ahi[i] = *(const float2*)&As[row + 8][kk + 2 * tig];
            }
            #pragma unroll
            for (int j = 0; j < 4; j++) {
                int col = wn * 32 + j * 8 + gid;
                float b0 = Bs[kk + 2 * tig][col];
                float b1 = Bs[kk + 2 * tig + 1][col];
                #pragma unroll
                for (int i = 0; i < 2; i++)
                    mma_tf32(Cacc[i][j], alo[i].x, ahi[i].x, alo[i].y, ahi[i].y, b0, b1);
            }
        }
        __syncthreads();
    }

    const float qs = (p == 0) ? SCALE : 1.0f;
    if (p == 2) {        // V: [d][s], direct float2
        float* g = g_v + (size_t)bn * D_ * S_;
        #pragma unroll
        for (int i = 0; i < 2; i++) {
            int r0 = wm * 32 + i * 16 + gid;
            float bi0 = bias[n * D_ + r0], bi1 = bias[n * D_ + r0 + 8];
            #pragma unroll
            for (int j = 0; j < 4; j++) {
                int col = s0 + wn * 32 + j * 8 + 2 * tig;
                *(float2*)&g[(size_t)r0 * S_ + col] =
                    make_float2(Cacc[i][j][0] + bi0, Cacc[i][j][1] + bi0);
                *(float2*)&g[(size_t)(r0 + 8) * S_ + col] =
                    make_float2(Cacc[i][j][2] + bi1, Cacc[i][j][3] + bi1);
            }
        }
    } else {             // Q / K: stage [s][d] in smem, coalesced float4 out
        #pragma unroll
        for (int i = 0; i < 2; i++) {
            int r0 = wm * 32 + i * 16 + gid;
            float bi0 = bias[n * D_ + r0], bi1 = bias[n * D_ + r0 + 8];
            #pragma unroll
            for (int j = 0; j < 4; j++) {
                int col = wn * 32 + j * 8 + 2 * tig;     // local s
                Ts[col][r0]         = (Cacc[i][j][0] + bi0) * qs;
                Ts[col + 1][r0]     = (Cacc[i][j][1] + bi0) * qs;
                Ts[col][r0 + 8]     = (Cacc[i][j][2] + bi1) * qs;
                Ts[col + 1][r0 + 8] = (Cacc[i][j][3] + bi1) * qs;
            }
        }
        __syncthreads();
        float* g = ((p == 0) ? g_q : g_k) + (size_t)bn * S_ * D_;
        #pragma unroll
        for (int r = 0; r < 8; r++) {
            int i4 = tid + r * 128;
            int ss = i4 >> 4, d4 = (i4 & 15) * 4;
            *(float4*)&g[(size_t)(s0 + ss) * D_ + d4] = *(const float4*)&Ts[ss][d4];
        }
    }
}

// ===========================================================================
// Flash attention, unshifted softmax, all-LDS.64 fragments.
// q-tile 128 (4 warps x 32 rows), kv-tile 64 (8 n-atoms), d=64.
// Qs[128][72] ([q][d]) | Ks[64][72] ([kv][d]) | Vs[64][72] ([d][kv]) |
// Ps[128][72] ([q][kv]) = 110592 B -> 2 CTAs/SM, grid 18x16 = one wave.
// ===========================================================================
extern __shared__ float s_at[];

__global__ __launch_bounds__(128) void attn_kernel()
{
    float (*Qs)[72] = (float (*)[72])(s_at);
    float (*Ks)[72] = (float (*)[72])(s_at + 128 * 72);
    float (*Vs)[72] = (float (*)[72])(s_at + 192 * 72);
    float (*Ps)[72] = (float (*)[72])(s_at + 256 * 72);

    const int bn = blockIdx.y;
    const int b = bn >> 3, n = bn & 7;
    const int q0 = blockIdx.x * QT;
    const int tid = threadIdx.x;
    const int wid = tid >> 5, lane = tid & 31;
    const int gid = lane >> 2, tig = lane & 3;
    const int qr  = wid * 32;

    const float* Q = g_q + (size_t)bn * S_ * D_;  // [s][d] pre-scaled
    const float* K = g_k + (size_t)bn * S_ * D_;  // [s][d]
    const float* V = g_v + (size_t)bn * D_ * S_;  // [d][s]

    #pragma unroll
    for (int r = 0; r < 16; r++) {
        int i4 = tid + r * 128;
        int row = i4 >> 4, seg = (i4 & 15) * 4;
        *(float4*)&Qs[row][seg] = *(const float4*)&Q[(size_t)(q0 + row) * D_ + seg];
    }

    float sum[2][2] = {};
    float O[2][8][4] = {};

    for (int k0 = 0; k0 < S_; k0 += 64) {
        __syncthreads();             // prev PV done with Ks/Vs (+Q visible, iter 0)
        #pragma unroll
        for (int r = 0; r < 8; r++) {
            int i4 = tid + r * 128;
            int row = i4 >> 4, seg = (i4 & 15) * 4;
            *(float4*)&Ks[row][seg] = *(const float4*)&K[(size_t)(k0 + row) * D_ + seg];
            *(float4*)&Vs[row][seg] = *(const float4*)&V[(size_t)row * S_ + k0 + seg];
        }
        __syncthreads();

        // S = Q K^T   (A: Qs[q][d]; B: Ks[kv][d] read as [n][k] -> float2)
        float Sc[2][8][4] = {};
        #pragma unroll
        for (int kk = 0; kk < 64; kk += 8) {
            float2 alo[2], ahi[2];
            #pragma unroll
            for (int i = 0; i < 2; i++) {
                int row = qr + i * 16 + gid;
                alo[i] = *(const float2*)&Qs[row][kk + 2 * tig];
                ahi[i] = *(const float2*)&Qs[row + 8][kk + 2 * tig];
            }
            #pragma unroll
            for (int j = 0; j < 8; j++) {
                float2 bb = *(const float2*)&Ks[j * 8 + gid][kk + 2 * tig];
                #pragma unroll
                for (int i = 0; i < 2; i++)
                    mma_tf32(Sc[i][j], alo[i].x, ahi[i].x, alo[i].y, ahi[i].y, bb.x, bb.y);
            }
        }

        // unshifted exp + local sum + P store (own rows only)
        #pragma unroll
        for (int i = 0; i < 2; i++) {
            int row0 = qr + i * 16 + gid;
            #pragma unroll
            for (int j = 0; j < 8; j++) {
                float e0 = __expf(Sc[i][j][0]);
                float e1 = __expf(Sc[i][j][1]);
                float e2 = __expf(Sc[i][j][2]);
                float e3 = __expf(Sc[i][j][3]);
                sum[i][0] += e0 + e1;
                sum[i][1] += e2 + e3;
                int col = j * 8 + 2 * tig;
                *(float2*)&Ps[row0][col]     = make_float2(tf32r(e0), tf32r(e1));
                *(float2*)&Ps[row0 + 8][col] = make_float2(tf32r(e2), tf32r(e3));
            }
        }
        __syncwarp();

        // O += P @ V   (A: Ps[q][kv]; B: Vs[d][kv] read as [n][k] -> float2)
        #pragma unroll
        for (int kk = 0; kk < 64; kk += 8) {
            float2 alo[2], ahi[2];
            #pragma unroll
            for (int i = 0; i < 2; i++) {
                int row = qr + i * 16 + gid;
                alo[i] = *(const float2*)&Ps[row][kk + 2 * tig];
                ahi[i] = *(const float2*)&Ps[row + 8][kk + 2 * tig];
            }
            #pragma unroll
            for (int j = 0; j < 8; j++) {
                float2 bb = *(const float2*)&Vs[j * 8 + gid][kk + 2 * tig];
                #pragma unroll
                for (int i = 0; i < 2; i++)
                    mma_tf32(O[i][j], alo[i].x, ahi[i].x, alo[i].y, ahi[i].y, bb.x, bb.y);
            }
        }
    }

    float inv[2][2];
    #pragma unroll
    for (int i = 0; i < 2; i++)
        #pragma unroll
        for (int h = 0; h < 2; h++) {
            float s = sum[i][h];
            s += __shfl_xor_sync(0xffffffffu, s, 1);
            s += __shfl_xor_sync(0xffffffffu, s, 2);
            inv[i][h] = 1.f / s;
        }

    float* A = g_attn + ((size_t)b * S_ + q0) * (NH * D_) + n * D_;
    #pragma unroll
    for (int i = 0; i < 2; i++) {
        int row0 = qr + i * 16 + gid;
        #pragma unroll
        for (int j = 0; j < 8; j++) {
            int col = j * 8 + 2 * tig;
            *(float2*)&A[(size_t)row0 * (NH * D_) + col] =
                make_float2(O[i][j][0] * inv[i][0], O[i][j][1] * inv[i][0]);
            *(float2*)&A[(size_t)(row0 + 8) * (NH * D_) + col] =
                make_float2(O[i][j][2] * inv[i][1], O[i][j][3] * inv[i][1]);
        }
    }
}

// ===========================================================================
// Output projection as out^T[s][c] = attn[s][:] . Wo[c][:]^T.
// A = attn[s][j] direct (As stride 40); B = Wo[c][j] as [n][k] (Bs stride 40).
// Output staged [c][s] in smem -> coalesced float4 stores to out[c][s].
// grid (36, 8, 2), block 128, warp 32s x 32c.
// ===========================================================================
__global__ __launch_bounds__(128) void oproj_kernel(
    const float* __restrict__ Wo, const float* __restrict__ bo,
    float* __restrict__ out)
{
    __shared__ float sbuf[5120];                  // As(2560) | Bs(2560); Ts(4352)
    float (*As)[40] = (float (*)[40])sbuf;
    float (*Bs)[40] = (float (*)[40])(sbuf + 2560);
    float (*Ts)[68] = (float (*)[68])sbuf;        // staging [c][s]

    const int b  = blockIdx.z;
    const int c0 = blockIdx.y * 64;
    const int s0 = blockIdx.x * 64;

    const int tid = threadIdx.x;
    const int wid = tid >> 5, lane = tid & 31;
    const int gid = lane >> 2, tig = lane & 3;
    const int wm  = wid >> 1, wn = wid & 1;   // wm: s-half, wn: c-half

    const float* A = g_attn + ((size_t)b * S_ + s0) * C_;
    float Cacc[2][4][4] = {};

    for (int j0 = 0; j0 < C_; j0 += 32) {
        #pragma unroll
        for (int r = 0; r < 4; r++) {
            int i4 = tid + r * 128;
            int rr = i4 >> 3, j4 = (i4 & 7) * 4;
            float4 va = *(const float4*)&A[(size_t)rr * C_ + j0 + j4];
            As[rr][j4]     = tf32r(va.x); As[rr][j4 + 1] = tf32r(va.y);
            As[rr][j4 + 2] = tf32r(va.z); As[rr][j4 + 3] = tf32r(va.w);
            float4 vb = *(const float4*)&Wo[(size_t)(c0 + rr) * C_ + j0 + j4];
            Bs[rr][j4]     = tf32r(vb.x); Bs[rr][j4 + 1] = tf32r(vb.y);
            Bs[rr][j4 + 2] = tf32r(vb.z); Bs[rr][j4 + 3] = tf32r(vb.w);
        }
        __syncthreads();

        #pragma unroll
        for (int kk = 0; kk < 32; kk += 8) {
            float2 alo[2], ahi[2];
            #pragma unroll
            for (int i = 0; i < 2; i++) {
                int row = wm * 32 + i * 16 + gid;
                alo[i] = *(const float2*)&As[row][kk + 2 * tig];
                ahi[i] = *(const float2*)&As[row + 8][kk + 2 * tig];
            }
            #pragma unroll
            for (int j = 0; j < 4; j++) {
                float2 bb = *(const float2*)&Bs[wn * 32 + j * 8 + gid][kk + 2 * tig];
                #pragma unroll
                for (int i = 0; i < 2; i++)
                    mma_tf32(Cacc[i][j], alo[i].x, ahi[i].x, alo[i].y, ahi[i].y, bb.x, bb.y);
            }
        }
        __syncthreads();
    }

    // Stage C (rows s, cols c) into Ts[c][s] with bias, then coalesced out.
    #pragma unroll
    for (int i = 0; i < 2; i++) {
        int r0 = wm * 32 + i * 16 + gid;              // local s
        #pragma unroll
        for (int j = 0; j < 4; j++) {
            int cl = wn * 32 + j * 8 + 2 * tig;       // local c
            float b0 = bo[c0 + cl], b1 = bo[c0 + cl + 1];
            Ts[cl][r0]         = Cacc[i][j][0] + b0;
            Ts[cl + 1][r0]     = Cacc[i][j][1] + b1;
            Ts[cl][r0 + 8]     = Cacc[i][j][2] + b0;
            Ts[cl + 1][r0 + 8] = Cacc[i][j][3] + b1;
        }
    }
    __syncthreads();
    float* ob = out + ((size_t)b * C_ + c0) * S_ + s0;
    #pragma unroll
    for (int r = 0; r < 8; r++) {
        int i4 = tid + r * 128;
        int cc = i4 >> 4, s4 = (i4 & 15) * 4;
        *(float4*)&ob[(size_t)cc * S_ + s4] = *(const float4*)&Ts[cc][s4];
    }
}

// ---------------------------------------------------------------------------
extern "C" void kernel_launch(void* const* d_in, const int* in_sizes, int n_in,
                              void* d_out, int out_size)
{
    const float* x  = (const float*)d_in[0];
    const float* Wq = (const float*)d_in[1];
    const float* bq = (const float*)d_in[2];
    const float* Wk = (const float*)d_in[3];
    const float* bk = (const float*)d_in[4];
    const float* Wv = (const float*)d_in[5];
    const float* bv = (const float*)d_in[6];
    const float* Wo = (const float*)d_in[7];
    const float* bo = (const float*)d_in[8];
    float* out = (float*)d_out;

    const int attn_smem = 384 * 72 * sizeof(float);   // 110592
    cudaFuncSetAttribute(attn_kernel,
                         cudaFuncAttributeMaxDynamicSharedMemorySize, attn_smem);

    proj_kernel <<<dim3(S_ / 64, B_ * NH, 3), 128>>>(x, Wq, bq, Wk, bk, Wv, bv);
    attn_kernel <<<dim3(S_ / QT, B_ * NH), 128, attn_smem>>>();
    oproj_kernel<<<dim3(S_ / 64, C_ / 64, B_), 128>>>(Wo, bo, out);
}

// round 13
// speedup vs baseline: 1.1384x; 1.1384x over previous
#include <cuda_runtime.h>
#include <cstdint>

#define B_  2
#define C_  512
#define NH  8
#define D_  64
#define S_  2304
#define SCALE 0.125f
#define QT  128

// ---------------------------------------------------------------------------
__device__ __forceinline__ float tf32r(float f) {
    unsigned r; asm("cvt.rna.tf32.f32 %0, %1;" : "=r"(r) : "f"(f));
    return __uint_as_float(r);
}
__device__ __forceinline__ void mma_tf32(float c[4],
                                         float a0, float a1, float a2, float a3,
                                         float b0, float b1) {
    asm volatile(
        "mma.sync.aligned.m16n8k8.row.col.f32.tf32.tf32.f32 "
        "{%0,%1,%2,%3}, {%4,%5,%6,%7}, {%8,%9}, {%0,%1,%2,%3};\n"
        : "+f"(c[0]), "+f"(c[1]), "+f"(c[2]), "+f"(c[3])
        : "r"(__float_as_uint(a0)), "r"(__float_as_uint(a1)),
          "r"(__float_as_uint(a2)), "r"(__float_as_uint(a3)),
          "r"(__float_as_uint(b0)), "r"(__float_as_uint(b1)));
}

// Scratch ------------------------------------------------------------------
__device__ float g_q[B_ * NH * S_ * D_];    // [bn][s][d]  (scale folded)
__device__ float g_k[B_ * NH * S_ * D_];    // [bn][s][d]
__device__ float g_v[B_ * NH * D_ * S_];    // [bn][d][s]
__device__ float g_attn[B_ * S_ * NH * D_]; // [b][s][n*64+d]

// ===========================================================================
// QKV projection — R11 mainloop (scalar fragments, As stride 36 / Bs 72),
// epilogue: Q,K -> [s][d] smem-staged float4; V -> [d][s] direct float2.
// grid (36, 16, 3), block 128.
// ===========================================================================
__global__ __launch_bounds__(128) void proj_kernel(
    const float* __restrict__ x,
    const float* __restrict__ Wq, const float* __restrict__ bq,
    const float* __restrict__ Wk, const float* __restrict__ bk,
    const float* __restrict__ Wv, const float* __restrict__ bv)
{
    __shared__ float sbuf[4608];                 // As(2304) | Bs(2304); Ts(4352)
    float (*As)[36] = (float (*)[36])sbuf;
    float (*Bs)[72] = (float (*)[72])(sbuf + 2304);
    float (*Ts)[68] = (float (*)[68])sbuf;       // epilogue staging [s][d]

    const int p  = blockIdx.z;
    const int bn = blockIdx.y;
    const int b  = bn >> 3, n = bn & 7;
    const int s0 = blockIdx.x * 64;

    const float* W    = (p == 0) ? Wq : (p == 1) ? Wk : Wv;
    const float* bias = (p == 0) ? bq : (p == 1) ? bk : bv;

    const int tid  = threadIdx.x;
    const int wid  = tid >> 5, lane = tid & 31;
    const int gid  = lane >> 2, tig = lane & 3;
    const int wm   = wid >> 1, wn = wid & 1;

    const float* xb = x + (size_t)b * C_ * S_ + s0;
    const float* Wn = W + n * D_ * C_;

    float Cacc[2][4][4] = {};

    for (int k0 = 0; k0 < C_; k0 += 32) {
        #pragma unroll
        for (int r = 0; r < 4; r++) {
            int i4 = tid + r * 128;
            int dd = i4 >> 3, c4 = (i4 & 7) * 4;
            float4 v = *(const float4*)&Wn[dd * C_ + k0 + c4];
            As[dd][c4]     = tf32r(v.x); As[dd][c4 + 1] = tf32r(v.y);
            As[dd][c4 + 2] = tf32r(v.z); As[dd][c4 + 3] = tf32r(v.w);
        }
        #pragma unroll
        for (int r = 0; r < 4; r++) {
            int i4 = tid + r * 128;
            int cc = i4 >> 4, s4 = (i4 & 15) * 4;
            float4 v = *(const float4*)&xb[(size_t)(k0 + cc) * S_ + s4];
            Bs[cc][s4]     = tf32r(v.x); Bs[cc][s4 + 1] = tf32r(v.y);
            Bs[cc][s4 + 2] = tf32r(v.z); Bs[cc][s4 + 3] = tf32r(v.w);
        }
        __syncthreads();

        #pragma unroll
        for (int kk = 0; kk < 32; kk += 8) {
            float a[2][4];
            #pragma unroll
            for (int i = 0; i < 2; i++) {
                int row = wm * 32 + i * 16;
                a[i][0] = As[row + gid][kk + tig];
                a[i][1] = As[row + gid + 8][kk + tig];
                a[i][2] = As[row + gid][kk + tig + 4];
                a[i][3] = As[row + gid + 8][kk + tig + 4];
            }
            #pragma unroll
            for (int j = 0; j < 4; j++) {
                int col = wn * 32 + j * 8 + gid;
                float b0 = Bs[kk + tig][col];
                float b1 = Bs[kk + tig + 4][col];
                #pragma unroll
                for (int i = 0; i < 2; i++)
                    mma_tf32(Cacc[i][j], a[i][0], a[i][1], a[i][2], a[i][3], b0, b1);
            }
        }
        __syncthreads();
    }

    const float qs = (p == 0) ? SCALE : 1.0f;
    if (p == 2) {        // V: [d][s], direct float2
        float* g = g_v + (size_t)bn * D_ * S_;
        #pragma unroll
        for (int i = 0; i < 2; i++) {
            int r0 = wm * 32 + i * 16 + gid;
            float bi0 = bias[n * D_ + r0], bi1 = bias[n * D_ + r0 + 8];
            #pragma unroll
            for (int j = 0; j < 4; j++) {
                int col = s0 + wn * 32 + j * 8 + 2 * tig;
                *(float2*)&g[(size_t)r0 * S_ + col] =
                    make_float2(Cacc[i][j][0] + bi0, Cacc[i][j][1] + bi0);
                *(float2*)&g[(size_t)(r0 + 8) * S_ + col] =
                    make_float2(Cacc[i][j][2] + bi1, Cacc[i][j][3] + bi1);
            }
        }
    } else {             // Q / K: stage [s][d] in smem, coalesced float4 out
        #pragma unroll
        for (int i = 0; i < 2; i++) {
            int r0 = wm * 32 + i * 16 + gid;
            float bi0 = bias[n * D_ + r0], bi1 = bias[n * D_ + r0 + 8];
            #pragma unroll
            for (int j = 0; j < 4; j++) {
                int col = wn * 32 + j * 8 + 2 * tig;     // local s
                Ts[col][r0]         = (Cacc[i][j][0] + bi0) * qs;
                Ts[col + 1][r0]     = (Cacc[i][j][1] + bi0) * qs;
                Ts[col][r0 + 8]     = (Cacc[i][j][2] + bi1) * qs;
                Ts[col + 1][r0 + 8] = (Cacc[i][j][3] + bi1) * qs;
            }
        }
        __syncthreads();
        float* g = ((p == 0) ? g_q : g_k) + (size_t)bn * S_ * D_;
        #pragma unroll
        for (int r = 0; r < 8; r++) {
            int i4 = tid + r * 128;
            int ss = i4 >> 4, d4 = (i4 & 15) * 4;
            *(float4*)&g[(size_t)(s0 + ss) * D_ + d4] = *(const float4*)&Ts[ss][d4];
        }
    }
}

// ===========================================================================
// Flash attention: k-permuted fragments, P STAYS IN REGISTERS (QK C-frag ==
// PV A-frag), unshifted softmax, double-buffered K/V, 1 sync per chunk.
// q-tile 128 (4 warps x 32 rows), kv-tile 64, d=64.
// Smem: Qs[128][72] | Ks[2][64][72] | Vs[2][64][72] = 110592 B -> 2 CTAs/SM.
// ===========================================================================
extern __shared__ float s_at[];

__global__ __launch_bounds__(128) void attn_kernel()
{
    float (*Qs)[72] = (float (*)[72])(s_at);
    float (*Ks)[64][72] = (float (*)[64][72])(s_at + 128 * 72);
    float (*Vs)[64][72] = (float (*)[64][72])(s_at + 256 * 72);

    const int bn = blockIdx.y;
    const int b = bn >> 3, n = bn & 7;
    const int q0 = blockIdx.x * QT;
    const int tid = threadIdx.x;
    const int wid = tid >> 5, lane = tid & 31;
    const int gid = lane >> 2, tig = lane & 3;
    const int qr  = wid * 32;

    const float* Q = g_q + (size_t)bn * S_ * D_;  // [s][d] pre-scaled
    const float* K = g_k + (size_t)bn * S_ * D_;  // [s][d]
    const float* V = g_v + (size_t)bn * D_ * S_;  // [d][s]

    #pragma unroll
    for (int r = 0; r < 16; r++) {
        int i4 = tid + r * 128;
        int row = i4 >> 4, seg = (i4 & 15) * 4;
        *(float4*)&Qs[row][seg] = *(const float4*)&Q[(size_t)(q0 + row) * D_ + seg];
    }

    const int ldrow = tid >> 4, ldseg = (tid & 15) * 4;
    auto load_kv = [&](int c, int buf) {
        int k0 = c * 64;
        #pragma unroll
        for (int r = 0; r < 8; r++) {
            int row = ldrow + r * 8;
            *(float4*)&Ks[buf][row][ldseg] = *(const float4*)&K[(size_t)(k0 + row) * D_ + ldseg];
            *(float4*)&Vs[buf][row][ldseg] = *(const float4*)&V[(size_t)row * S_ + k0 + ldseg];
        }
    };

    float sum[2][2] = {};
    float O[2][8][4] = {};

    load_kv(0, 0);
    __syncthreads();                 // Q + buf0 visible

    for (int c = 0; c < S_ / 64; c++) {
        const int cur = c & 1;
        if (c + 1 < S_ / 64) load_kv(c + 1, cur ^ 1);   // prefetch other buffer

        // S = Q K^T   (k-permuted: A float2 from Qs, B float2 from Ks)
        float Sc[2][8][4] = {};
        #pragma unroll
        for (int kk = 0; kk < 64; kk += 8) {
            float2 alo[2], ahi[2];
            #pragma unroll
            for (int i = 0; i < 2; i++) {
                int row = qr + i * 16 + gid;
                alo[i] = *(const float2*)&Qs[row][kk + 2 * tig];
                ahi[i] = *(const float2*)&Qs[row + 8][kk + 2 * tig];
            }
            #pragma unroll
            for (int j = 0; j < 8; j++) {
                float2 bb = *(const float2*)&Ks[cur][j * 8 + gid][kk + 2 * tig];
                #pragma unroll
                for (int i = 0; i < 2; i++)
                    mma_tf32(Sc[i][j], alo[i].x, ahi[i].x, alo[i].y, ahi[i].y, bb.x, bb.y);
            }
        }

        // exp in regs; QK C-frag IS the PV A-frag (k-permuted): feed directly
        #pragma unroll
        for (int j = 0; j < 8; j++) {
            float e[2][4];
            #pragma unroll
            for (int i = 0; i < 2; i++) {
                e[i][0] = __expf(Sc[i][j][0]);
                e[i][1] = __expf(Sc[i][j][1]);
                e[i][2] = __expf(Sc[i][j][2]);
                e[i][3] = __expf(Sc[i][j][3]);
                sum[i][0] += e[i][0] + e[i][1];
                sum[i][1] += e[i][2] + e[i][3];
            }
            #pragma unroll
            for (int nn = 0; nn < 8; nn++) {
                float2 bb = *(const float2*)&Vs[cur][nn * 8 + gid][j * 8 + 2 * tig];
                #pragma unroll
                for (int i = 0; i < 2; i++)
                    mma_tf32(O[i][nn], e[i][0], e[i][2], e[i][1], e[i][3], bb.x, bb.y);
            }
        }
        __syncthreads();             // compute on cur done; prefetch visible
    }

    float inv[2][2];
    #pragma unroll
    for (int i = 0; i < 2; i++)
        #pragma unroll
        for (int h = 0; h < 2; h++) {
            float s = sum[i][h];
            s += __shfl_xor_sync(0xffffffffu, s, 1);
            s += __shfl_xor_sync(0xffffffffu, s, 2);
            inv[i][h] = 1.f / s;
        }

    float* A = g_attn + ((size_t)b * S_ + q0) * (NH * D_) + n * D_;
    #pragma unroll
    for (int i = 0; i < 2; i++) {
        int row0 = qr + i * 16 + gid;
        #pragma unroll
        for (int j = 0; j < 8; j++) {
            int col = j * 8 + 2 * tig;
            *(float2*)&A[(size_t)row0 * (NH * D_) + col] =
                make_float2(O[i][j][0] * inv[i][0], O[i][j][1] * inv[i][0]);
            *(float2*)&A[(size_t)(row0 + 8) * (NH * D_) + col] =
                make_float2(O[i][j][2] * inv[i][1], O[i][j][3] * inv[i][1]);
        }
    }
}

// ===========================================================================
// Output projection (R12 version): out^T[s][c] = attn[s][:] . Wo[c][:]^T.
// ===========================================================================
__global__ __launch_bounds__(128) void oproj_kernel(
    const float* __restrict__ Wo, const float* __restrict__ bo,
    float* __restrict__ out)
{
    __shared__ float sbuf[5120];                  // As(2560) | Bs(2560); Ts(4352)
    float (*As)[40] = (float (*)[40])sbuf;
    float (*Bs)[40] = (float (*)[40])(sbuf + 2560);
    float (*Ts)[68] = (float (*)[68])sbuf;        // staging [c][s]

    const int b  = blockIdx.z;
    const int c0 = blockIdx.y * 64;
    const int s0 = blockIdx.x * 64;

    const int tid = threadIdx.x;
    const int wid = tid >> 5, lane = tid & 31;
    const int gid = lane >> 2, tig = lane & 3;
    const int wm  = wid >> 1, wn = wid & 1;

    const float* A = g_attn + ((size_t)b * S_ + s0) * C_;
    float Cacc[2][4][4] = {};

    for (int j0 = 0; j0 < C_; j0 += 32) {
        #pragma unroll
        for (int r = 0; r < 4; r++) {
            int i4 = tid + r * 128;
            int rr = i4 >> 3, j4 = (i4 & 7) * 4;
            float4 va = *(const float4*)&A[(size_t)rr * C_ + j0 + j4];
            As[rr][j4]     = tf32r(va.x); As[rr][j4 + 1] = tf32r(va.y);
            As[rr][j4 + 2] = tf32r(va.z); As[rr][j4 + 3] = tf32r(va.w);
            float4 vb = *(const float4*)&Wo[(size_t)(c0 + rr) * C_ + j0 + j4];
            Bs[rr][j4]     = tf32r(vb.x); Bs[rr][j4 + 1] = tf32r(vb.y);
            Bs[rr][j4 + 2] = tf32r(vb.z); Bs[rr][j4 + 3] = tf32r(vb.w);
        }
        __syncthreads();

        #pragma unroll
        for (int kk = 0; kk < 32; kk += 8) {
            float2 alo[2], ahi[2];
            #pragma unroll
            for (int i = 0; i < 2; i++) {
                int row = wm * 32 + i * 16 + gid;
                alo[i] = *(const float2*)&As[row][kk + 2 * tig];
                ahi[i] = *(const float2*)&As[row + 8][kk + 2 * tig];
            }
            #pragma unroll
            for (int j = 0; j < 4; j++) {
                float2 bb = *(const float2*)&Bs[wn * 32 + j * 8 + gid][kk + 2 * tig];
                #pragma unroll
                for (int i = 0; i < 2; i++)
                    mma_tf32(Cacc[i][j], alo[i].x, ahi[i].x, alo[i].y, ahi[i].y, bb.x, bb.y);
            }
        }
        __syncthreads();
    }

    #pragma unroll
    for (int i = 0; i < 2; i++) {
        int r0 = wm * 32 + i * 16 + gid;              // local s
        #pragma unroll
        for (int j = 0; j < 4; j++) {
            int cl = wn * 32 + j * 8 + 2 * tig;       // local c
            float b0 = bo[c0 + cl], b1 = bo[c0 + cl + 1];
            Ts[cl][r0]         = Cacc[i][j][0] + b0;
            Ts[cl + 1][r0]     = Cacc[i][j][1] + b1;
            Ts[cl][r0 + 8]     = Cacc[i][j][2] + b0;
            Ts[cl + 1][r0 + 8] = Cacc[i][j][3] + b1;
        }
    }
    __syncthreads();
    float* ob = out + ((size_t)b * C_ + c0) * S_ + s0;
    #pragma unroll
    for (int r = 0; r < 8; r++) {
        int i4 = tid + r * 128;
        int cc = i4 >> 4, s4 = (i4 & 15) * 4;
        *(float4*)&ob[(size_t)cc * S_ + s4] = *(const float4*)&Ts[cc][s4];
    }
}

// ---------------------------------------------------------------------------
extern "C" void kernel_launch(void* const* d_in, const int* in_sizes, int n_in,
                              void* d_out, int out_size)
{
    const float* x  = (const float*)d_in[0];
    const float* Wq = (const float*)d_in[1];
    const float* bq = (const float*)d_in[2];
    const float* Wk = (const float*)d_in[3];
    const float* bk = (const float*)d_in[4];
    const float* Wv = (const float*)d_in[5];
    const float* bv = (const float*)d_in[6];
    const float* Wo = (const float*)d_in[7];
    const float* bo = (const float*)d_in[8];
    float* out = (float*)d_out;

    const int attn_smem = 384 * 72 * sizeof(float);   // 110592
    cudaFuncSetAttribute(attn_kernel,
                         cudaFuncAttributeMaxDynamicSharedMemorySize, attn_smem);

    proj_kernel <<<dim3(S_ / 64, B_ * NH, 3), 128>>>(x, Wq, bq, Wk, bk, Wv, bv);
    attn_kernel <<<dim3(S_ / QT, B_ * NH), 128, attn_smem>>>();
    oproj_kernel<<<dim3(S_ / 64, C_ / 64, B_), 128>>>(Wo, bo, out);
}